// round 1
// baseline (speedup 1.0000x reference)
#include <cuda_runtime.h>
#include <math.h>

// ---------------------------------------------------------------------------
// Problem constants: B=8, H=W=128, NW=8, D=256
//   tokens M = 8*128*128 = 131072
//   windows = 8*64 = 512, window tokens N = 256
// ---------------------------------------------------------------------------

#define M_TOK 131072
#define DIM   256

// Scratch (device globals: allocation-free kernel_launch)
__device__ float g_q [33554432];
__device__ float g_k [33554432];
__device__ float g_v [33554432];
__device__ float g_qw[33554432];
__device__ float g_kw[33554432];
__device__ float g_vw[33554432];
__device__ float g_s [33554432];
__device__ float g_ow[33554432];
__device__ float g_a [33554432];
__device__ float g_t [33554432];
__device__ float g_ln[33554432];
__device__ float g_f0[33554432];
__device__ float g_cat[67108864];   // [131072, 512]
__device__ float g_h [268435456];   // [131072, 2048]

// ---------------------------------------------------------------------------
// Generic 128x128x16 fp32 GEMM, 256 threads, 8x8 per thread.
// C[M,N] = A[M,K] @ B[K,N]            (TRANSB=false)
// C[M,N] = A[M,K] @ B[N,K]^T          (TRANSB=true)
// Batched via blockIdx.z with element strides sA/sB/sC.
// SCORES: C = C*scale + mask[z&63] (mask is [64,256,256], N must be 256)
// All dims assumed divisible by tile sizes (true for this problem).
// ---------------------------------------------------------------------------
template<bool TRANSB, bool SCORES>
__global__ __launch_bounds__(256)
void gemm128(const float* __restrict__ A, const float* __restrict__ B,
             float* __restrict__ C, int M, int N, int K,
             size_t sA, size_t sB, size_t sC,
             float scale, const float* __restrict__ mask)
{
    int z = blockIdx.z;
    A += (size_t)z * sA;
    B += (size_t)z * sB;
    C += (size_t)z * sC;

    __shared__ float As[16][128];
    __shared__ float Bs[16][128];

    int tid = threadIdx.x;
    int tx = tid & 15;        // 0..15  -> 8 output cols each
    int ty = tid >> 4;        // 0..15  -> 8 output rows each
    int rowBase = blockIdx.y * 128;
    int colBase = blockIdx.x * 128;

    float acc[8][8];
#pragma unroll
    for (int i = 0; i < 8; i++)
#pragma unroll
        for (int j = 0; j < 8; j++) acc[i][j] = 0.f;

    for (int k0 = 0; k0 < K; k0 += 16) {
        // A tile: [128 rows][16 k] -> As[k][row]  (512 float4 loads)
#pragma unroll 2
        for (int l = tid; l < 512; l += 256) {
            int r = l >> 2;
            int c4 = (l & 3) << 2;
            float4 vv = *(const float4*)&A[(size_t)(rowBase + r) * K + k0 + c4];
            As[c4 + 0][r] = vv.x;
            As[c4 + 1][r] = vv.y;
            As[c4 + 2][r] = vv.z;
            As[c4 + 3][r] = vv.w;
        }
        if (TRANSB) {
            // B tile from [N,K]: rows = output cols -> Bs[k][col]
#pragma unroll 2
            for (int l = tid; l < 512; l += 256) {
                int r = l >> 2;
                int c4 = (l & 3) << 2;
                float4 vv = *(const float4*)&B[(size_t)(colBase + r) * K + k0 + c4];
                Bs[c4 + 0][r] = vv.x;
                Bs[c4 + 1][r] = vv.y;
                Bs[c4 + 2][r] = vv.z;
                Bs[c4 + 3][r] = vv.w;
            }
        } else {
            // B tile from [K,N]: coalesced float4 rows
#pragma unroll 2
            for (int l = tid; l < 512; l += 256) {
                int r = l >> 5;
                int c4 = (l & 31) << 2;
                *(float4*)&Bs[r][c4] = *(const float4*)&B[(size_t)(k0 + r) * N + colBase + c4];
            }
        }
        __syncthreads();

#pragma unroll
        for (int kk = 0; kk < 16; kk++) {
            float4 a0 = *(const float4*)&As[kk][ty * 8];
            float4 a1 = *(const float4*)&As[kk][ty * 8 + 4];
            float4 b0 = *(const float4*)&Bs[kk][tx * 8];
            float4 b1 = *(const float4*)&Bs[kk][tx * 8 + 4];
            float av[8] = {a0.x, a0.y, a0.z, a0.w, a1.x, a1.y, a1.z, a1.w};
            float bv[8] = {b0.x, b0.y, b0.z, b0.w, b1.x, b1.y, b1.z, b1.w};
#pragma unroll
            for (int i = 0; i < 8; i++)
#pragma unroll
                for (int j = 0; j < 8; j++)
                    acc[i][j] = fmaf(av[i], bv[j], acc[i][j]);
        }
        __syncthreads();
    }

    const float* mbase = nullptr;
    if (SCORES) mbase = mask + (size_t)(z & 63) * 65536;

#pragma unroll
    for (int i = 0; i < 8; i++) {
        int r = rowBase + ty * 8 + i;
        size_t off = (size_t)r * N + colBase + tx * 8;
#pragma unroll
        for (int j4 = 0; j4 < 2; j4++) {
            float4 vv;
            vv.x = acc[i][j4 * 4 + 0];
            vv.y = acc[i][j4 * 4 + 1];
            vv.z = acc[i][j4 * 4 + 2];
            vv.w = acc[i][j4 * 4 + 3];
            if (SCORES) {
                float4 mm = *(const float4*)&mbase[(size_t)r * 256 + colBase + tx * 8 + j4 * 4];
                vv.x = fmaf(vv.x, scale, mm.x);
                vv.y = fmaf(vv.y, scale, mm.y);
                vv.z = fmaf(vv.z, scale, mm.z);
                vv.w = fmaf(vv.w, scale, mm.w);
            }
            *(float4*)&C[off + j4 * 4] = vv;
        }
    }
}

// ---------------------------------------------------------------------------
// Roll(-8,-8) + window-partition gather:  [B,H*W,C] -> [512, 256, 256]
// dst[w=b*64+wy*8+wx][n=i*16+j][c] = src[b][ (wy*16+i+8)&127 ][ (wx*16+j+8)&127 ][c]
// ---------------------------------------------------------------------------
__global__ void permute_fwd(const float4* __restrict__ src, float4* __restrict__ dst)
{
    int e = blockIdx.x * 256 + threadIdx.x;         // over 512*256*64
    int c4 = e & 63;
    int n  = (e >> 6) & 255;
    int w  = e >> 14;
    int b  = w >> 6;
    int widx = w & 63;
    int wy = widx >> 3, wx = widx & 7;
    int i = n >> 4, j = n & 15;
    int h  = (wy * 16 + i + 8) & 127;
    int wc = (wx * 16 + j + 8) & 127;
    size_t sidx = ((size_t)(b * 16384 + h * 128 + wc) << 6) + c4;
    dst[e] = src[sidx];
}

// Inverse: merge + roll(+8,+8) scatter:  [512,256,256] -> [B,H*W,C]
__global__ void permute_bwd(float4* __restrict__ dst, const float4* __restrict__ src)
{
    int e = blockIdx.x * 256 + threadIdx.x;
    int c4 = e & 63;
    int n  = (e >> 6) & 255;
    int w  = e >> 14;
    int b  = w >> 6;
    int widx = w & 63;
    int wy = widx >> 3, wx = widx & 7;
    int i = n >> 4, j = n & 15;
    int h  = (wy * 16 + i + 8) & 127;
    int wc = (wx * 16 + j + 8) & 127;
    size_t didx = ((size_t)(b * 16384 + h * 128 + wc) << 6) + c4;
    dst[didx] = src[e];
}

// ---------------------------------------------------------------------------
// Row softmax over 256 cols. One warp per row, 8 rows per 256-thread block.
// ---------------------------------------------------------------------------
__global__ void softmax256(float* __restrict__ S)
{
    int row  = (blockIdx.x << 3) + (threadIdx.x >> 5);
    int lane = threadIdx.x & 31;
    float4* p = (float4*)(S + ((size_t)row << 8)) + lane * 2;
    float4 v0 = p[0], v1 = p[1];

    float mx = fmaxf(fmaxf(fmaxf(v0.x, v0.y), fmaxf(v0.z, v0.w)),
                     fmaxf(fmaxf(v1.x, v1.y), fmaxf(v1.z, v1.w)));
#pragma unroll
    for (int o = 16; o; o >>= 1) mx = fmaxf(mx, __shfl_xor_sync(0xffffffffu, mx, o));

    v0.x = __expf(v0.x - mx); v0.y = __expf(v0.y - mx);
    v0.z = __expf(v0.z - mx); v0.w = __expf(v0.w - mx);
    v1.x = __expf(v1.x - mx); v1.y = __expf(v1.y - mx);
    v1.z = __expf(v1.z - mx); v1.w = __expf(v1.w - mx);

    float s = v0.x + v0.y + v0.z + v0.w + v1.x + v1.y + v1.z + v1.w;
#pragma unroll
    for (int o = 16; o; o >>= 1) s += __shfl_xor_sync(0xffffffffu, s, o);

    float inv = 1.f / s;
    v0.x *= inv; v0.y *= inv; v0.z *= inv; v0.w *= inv;
    v1.x *= inv; v1.y *= inv; v1.z *= inv; v1.w *= inv;
    p[0] = v0; p[1] = v1;
}

// ---------------------------------------------------------------------------
// LayerNorm over 256 cols (eps=1e-5). One warp per row.
// ---------------------------------------------------------------------------
__global__ void layernorm256(const float* __restrict__ X,
                             const float* __restrict__ gamma,
                             const float* __restrict__ beta,
                             float* __restrict__ Y)
{
    int row  = (blockIdx.x << 3) + (threadIdx.x >> 5);
    int lane = threadIdx.x & 31;
    const float4* p = (const float4*)(X + ((size_t)row << 8)) + lane * 2;
    float4 v0 = p[0], v1 = p[1];

    float s  = v0.x + v0.y + v0.z + v0.w + v1.x + v1.y + v1.z + v1.w;
    float sq = v0.x*v0.x + v0.y*v0.y + v0.z*v0.z + v0.w*v0.w
             + v1.x*v1.x + v1.y*v1.y + v1.z*v1.z + v1.w*v1.w;
#pragma unroll
    for (int o = 16; o; o >>= 1) {
        s  += __shfl_xor_sync(0xffffffffu, s,  o);
        sq += __shfl_xor_sync(0xffffffffu, sq, o);
    }
    float mean = s * (1.f / 256.f);
    float var  = sq * (1.f / 256.f) - mean * mean;
    float rstd = rsqrtf(var + 1e-5f);

    const float4* gp = (const float4*)gamma + lane * 2;
    const float4* bp = (const float4*)beta  + lane * 2;
    float4 g0 = gp[0], g1 = gp[1], b0 = bp[0], b1 = bp[1];

    float4 o0, o1;
    o0.x = (v0.x - mean) * rstd * g0.x + b0.x;
    o0.y = (v0.y - mean) * rstd * g0.y + b0.y;
    o0.z = (v0.z - mean) * rstd * g0.z + b0.z;
    o0.w = (v0.w - mean) * rstd * g0.w + b0.w;
    o1.x = (v1.x - mean) * rstd * g1.x + b1.x;
    o1.y = (v1.y - mean) * rstd * g1.y + b1.y;
    o1.z = (v1.z - mean) * rstd * g1.z + b1.z;
    o1.w = (v1.w - mean) * rstd * g1.w + b1.w;

    float4* q = (float4*)(Y + ((size_t)row << 8)) + lane * 2;
    q[0] = o0; q[1] = o1;
}

// out = a + b, n4 float4 elements
__global__ void add2(const float4* __restrict__ a, const float4* __restrict__ b,
                     float4* __restrict__ o)
{
    size_t e = (size_t)blockIdx.x * 256 + threadIdx.x;
    float4 x = a[e], y = b[e];
    x.x += y.x; x.y += y.y; x.z += y.z; x.w += y.w;
    o[e] = x;
}

// cat[row, 0:256]=a[row], cat[row, 256:512]=b[row] ; e over 131072*128 float4
__global__ void concat2(const float4* __restrict__ a, const float4* __restrict__ b,
                        float4* __restrict__ o)
{
    size_t e = (size_t)blockIdx.x * 256 + threadIdx.x;
    size_t row = e >> 7;
    int col = (int)(e & 127);
    o[e] = (col < 64) ? a[(row << 6) + col] : b[(row << 6) + col - 64];
}

// exact GELU in-place: x * 0.5 * (1 + erf(x/sqrt(2)))
__global__ void gelu_ip(float4* __restrict__ x)
{
    size_t e = (size_t)blockIdx.x * 256 + threadIdx.x;
    float4 v = x[e];
    v.x = 0.5f * v.x * (1.f + erff(v.x * 0.70710678118654752f));
    v.y = 0.5f * v.y * (1.f + erff(v.y * 0.70710678118654752f));
    v.z = 0.5f * v.z * (1.f + erff(v.z * 0.70710678118654752f));
    v.w = 0.5f * v.w * (1.f + erff(v.w * 0.70710678118654752f));
    x[e] = v;
}

// ---------------------------------------------------------------------------
// Host orchestration
// ---------------------------------------------------------------------------
static void run_attn_block(const float* xq, const float* xkv, const float* mask,
                           const float* wq, const float* wk, const float* wv,
                           const float* wfc, const float* gam, const float* bet,
                           float* q, float* k, float* v,
                           float* qw, float* kw, float* vw,
                           float* s, float* ow, float* a, float* t, float* ln)
{
    dim3 gm(2, 1024, 1);           // N=256, M=131072
    dim3 gw(2, 2, 512);            // batched window gemms
    gemm128<false, false><<<gm, 256>>>(xq,  wq, q, M_TOK, 256, 256, 0, 0, 0, 0.f, nullptr);
    gemm128<false, false><<<gm, 256>>>(xkv, wk, k, M_TOK, 256, 256, 0, 0, 0, 0.f, nullptr);
    gemm128<false, false><<<gm, 256>>>(xkv, wv, v, M_TOK, 256, 256, 0, 0, 0, 0.f, nullptr);
    permute_fwd<<<32768, 256>>>((const float4*)q, (float4*)qw);
    permute_fwd<<<32768, 256>>>((const float4*)k, (float4*)kw);
    permute_fwd<<<32768, 256>>>((const float4*)v, (float4*)vw);
    // scores = Qw @ Kw^T / 16 + mask[w%64]
    gemm128<true, true><<<gw, 256>>>(qw, kw, s, 256, 256, 256,
                                     65536, 65536, 65536, 1.f / 16.f, mask);
    softmax256<<<16384, 256>>>(s);
    // Ow = P @ Vw
    gemm128<false, false><<<gw, 256>>>(s, vw, ow, 256, 256, 256,
                                       65536, 65536, 65536, 0.f, nullptr);
    permute_bwd<<<32768, 256>>>((float4*)a, (const float4*)ow);
    gemm128<false, false><<<gm, 256>>>(a, wfc, t, M_TOK, 256, 256, 0, 0, 0, 0.f, nullptr);
    layernorm256<<<16384, 256>>>(t, gam, bet, ln);
}

extern "C" void kernel_launch(void* const* d_in, const int* in_sizes, int n_in,
                              void* d_out, int out_size)
{
    const float* feat0 = (const float*)d_in[0];
    const float* feat1 = (const float*)d_in[1];
    const float* mask  = (const float*)d_in[2];
    // d_in[3..5]: width/height/n_window scalars (shapes hardcoded)
    const float* iwq  = (const float*)d_in[6];
    const float* iwk  = (const float*)d_in[7];
    const float* iwv  = (const float*)d_in[8];
    const float* iwfc = (const float*)d_in[9];
    const float* ig   = (const float*)d_in[10];
    const float* ib   = (const float*)d_in[11];
    const float* ewq  = (const float*)d_in[12];
    const float* ewk  = (const float*)d_in[13];
    const float* ewv  = (const float*)d_in[14];
    const float* ewfc = (const float*)d_in[15];
    const float* eg   = (const float*)d_in[16];
    const float* eb   = (const float*)d_in[17];
    const float* w1   = (const float*)d_in[18];
    const float* w2   = (const float*)d_in[19];
    const float* fg   = (const float*)d_in[20];
    const float* fb   = (const float*)d_in[21];
    float* out = (float*)d_out;

    float *q, *k, *v, *qw, *kw, *vw, *s, *ow, *a, *t, *ln, *f0, *cat, *h;
    cudaGetSymbolAddress((void**)&q,  g_q);
    cudaGetSymbolAddress((void**)&k,  g_k);
    cudaGetSymbolAddress((void**)&v,  g_v);
    cudaGetSymbolAddress((void**)&qw, g_qw);
    cudaGetSymbolAddress((void**)&kw, g_kw);
    cudaGetSymbolAddress((void**)&vw, g_vw);
    cudaGetSymbolAddress((void**)&s,  g_s);
    cudaGetSymbolAddress((void**)&ow, g_ow);
    cudaGetSymbolAddress((void**)&a,  g_a);
    cudaGetSymbolAddress((void**)&t,  g_t);
    cudaGetSymbolAddress((void**)&ln, g_ln);
    cudaGetSymbolAddress((void**)&f0, g_f0);
    cudaGetSymbolAddress((void**)&cat, g_cat);
    cudaGetSymbolAddress((void**)&h,  g_h);

    // ---- Block 1 (intra): q,k,v from feat0 ----
    run_attn_block(feat0, feat0, mask, iwq, iwk, iwv, iwfc, ig, ib,
                   q, k, v, qw, kw, vw, s, ow, a, t, ln);
    add2<<<32768, 256>>>((const float4*)feat0, (const float4*)ln, (float4*)f0);

    // ---- Block 2 (inter): q from f0, k,v from feat1 ----
    run_attn_block(f0, feat1, mask, ewq, ewk, ewv, ewfc, eg, eb,
                   q, k, v, qw, kw, vw, s, ow, a, t, ln);

    // FFN: concat([f0, ln]) @ w1 -> gelu -> @ w2 -> LN -> residual
    concat2<<<65536, 256>>>((const float4*)f0, (const float4*)ln, (float4*)cat);
    gemm128<false, false><<<dim3(16, 1024, 1), 256>>>(cat, w1, h,
                                                      M_TOK, 2048, 512, 0, 0, 0, 0.f, nullptr);
    gelu_ip<<<262144, 256>>>((float4*)h);
    gemm128<false, false><<<dim3(2, 1024, 1), 256>>>(h, w2, t,
                                                     M_TOK, 256, 2048, 0, 0, 0, 0.f, nullptr);
    layernorm256<<<16384, 256>>>(t, fg, fb, ln);
    add2<<<32768, 256>>>((const float4*)f0, (const float4*)ln, (float4*)out);
}

// round 6
// speedup vs baseline: 2.6754x; 2.6754x over previous
#include <cuda_runtime.h>
#include <math.h>
#include <stdint.h>

// ---------------------------------------------------------------------------
// Problem constants: B=8, H=W=128, NW=8, D=256
//   tokens M = 8*128*128 = 131072; windows = 512, window tokens N = 256
// ---------------------------------------------------------------------------
#define M_TOK 131072

// Scratch (device globals: allocation-free kernel_launch)
__device__ float g_q [33554432];
__device__ float g_k [33554432];
__device__ float g_v [33554432];
__device__ float g_qw[33554432];
__device__ float g_kw[33554432];
__device__ float g_vw[33554432];
__device__ float g_s [33554432];
__device__ float g_ow[33554432];
__device__ float g_a [33554432];
__device__ float g_t [33554432];
__device__ float g_ln[33554432];
__device__ float g_f0[33554432];
__device__ float g_cat[67108864];   // [131072, 512]
__device__ float g_h [268435456];   // [131072, 2048]
__device__ float g_wT[2097152];     // transposed+tf32 weights

// ---------------------------------------------------------------------------
// tf32 helpers
// ---------------------------------------------------------------------------
__device__ __forceinline__ float tf32r(float x) {
    float r;
    asm("cvt.rna.tf32.f32 %0, %1;" : "=f"(r) : "f"(x));
    return r;
}
__device__ __forceinline__ void ldsm4(uint32_t& r0, uint32_t& r1, uint32_t& r2,
                                      uint32_t& r3, uint32_t a) {
    asm volatile("ldmatrix.sync.aligned.m8n8.x4.shared.b16 {%0,%1,%2,%3}, [%4];"
                 : "=r"(r0), "=r"(r1), "=r"(r2), "=r"(r3) : "r"(a));
}
__device__ __forceinline__ void mma8(float* c, const uint32_t* a, const uint32_t* b) {
    asm volatile(
        "mma.sync.aligned.m16n8k8.row.col.f32.tf32.tf32.f32 "
        "{%0,%1,%2,%3},{%4,%5,%6,%7},{%8,%9},{%0,%1,%2,%3};"
        : "+f"(c[0]), "+f"(c[1]), "+f"(c[2]), "+f"(c[3])
        : "r"(a[0]), "r"(a[1]), "r"(a[2]), "r"(a[3]), "r"(b[0]), "r"(b[1]));
}
__device__ __forceinline__ float gelu1(float x) {
    return 0.5f * x * (1.f + erff(x * 0.70710678118654752f));
}

// ---------------------------------------------------------------------------
// Tensor-core tf32 GEMM. CTA tile 128x128, 8 warps of 64x32, K-chunk 16,
// double-buffered smem + register prefetch.
//   BK=0 : B is N-major [N,K] (row n contiguous in k)  -> C = A @ B^T
//   BK=1 : B is K-major [K,N] (row k contiguous in n)  -> C = A @ B
// Batched via blockIdx.z strides. SCORES: C = C*scale + mask[z&63].
// GELU: apply exact gelu to accumulator before store.
// Dims must be multiples of the tile (true here).
// ---------------------------------------------------------------------------
template<int BK, bool SCORES, bool GELU>
__global__ __launch_bounds__(256)
void gemm_tc(const float* __restrict__ A, const float* __restrict__ B,
             float* __restrict__ C, int M, int N, int K,
             size_t sA, size_t sB, size_t sC,
             float scale, const float* __restrict__ mask)
{
    __shared__ float As[2][2560];   // 128 rows x (16+4) pad
    __shared__ float Bs[2][2560];   // NMAJ: 128x20 ; KMAJ: 16x132

    const int tid  = threadIdx.x;
    const int lane = tid & 31;
    const int warp = tid >> 5;
    const int warpM = (warp & 1) * 64;
    const int warpN = (warp >> 1) * 32;
    const int rowBase = blockIdx.y * 128;
    const int colBase = blockIdx.x * 128;
    const int z = blockIdx.z;
    A += (size_t)z * sA;
    B += (size_t)z * sB;
    C += (size_t)z * sC;

    float acc[4][4][4];
#pragma unroll
    for (int i = 0; i < 4; i++)
#pragma unroll
        for (int t = 0; t < 4; t++)
#pragma unroll
            for (int r = 0; r < 4; r++) acc[i][t][r] = 0.f;

    // global-load coordinates
    const int ar  = tid >> 2;          // 0..63 (rows ar, ar+64)
    const int ac4 = (tid & 3) << 2;    // k offset within 16-chunk
    const int br  = tid >> 5;          // 0..7  (KMAJ rows br, br+8)
    const int bc4 = (tid & 31) << 2;   // n offset 0..124

    float4 pa0, pa1, pb0, pb1;

    auto loadAB = [&](int k0) {
        pa0 = *(const float4*)&A[(size_t)(rowBase + ar)      * K + k0 + ac4];
        pa1 = *(const float4*)&A[(size_t)(rowBase + ar + 64) * K + k0 + ac4];
        if (BK == 0) {
            pb0 = *(const float4*)&B[(size_t)(colBase + ar)      * K + k0 + ac4];
            pb1 = *(const float4*)&B[(size_t)(colBase + ar + 64) * K + k0 + ac4];
        } else {
            pb0 = *(const float4*)&B[(size_t)(k0 + br)     * N + colBase + bc4];
            pb1 = *(const float4*)&B[(size_t)(k0 + br + 8) * N + colBase + bc4];
        }
    };
    auto stsAB = [&](int buf) {
        float* a0 = &As[buf][ar * 20 + ac4];
        a0[0] = tf32r(pa0.x); a0[1] = tf32r(pa0.y); a0[2] = tf32r(pa0.z); a0[3] = tf32r(pa0.w);
        float* a1 = &As[buf][(ar + 64) * 20 + ac4];
        a1[0] = tf32r(pa1.x); a1[1] = tf32r(pa1.y); a1[2] = tf32r(pa1.z); a1[3] = tf32r(pa1.w);
        if (BK == 0) {
            float* b0 = &Bs[buf][ar * 20 + ac4];
            b0[0] = tf32r(pb0.x); b0[1] = tf32r(pb0.y); b0[2] = tf32r(pb0.z); b0[3] = tf32r(pb0.w);
            float* b1 = &Bs[buf][(ar + 64) * 20 + ac4];
            b1[0] = tf32r(pb1.x); b1[1] = tf32r(pb1.y); b1[2] = tf32r(pb1.z); b1[3] = tf32r(pb1.w);
        } else {
            float* b0 = &Bs[buf][br * 132 + bc4];
            b0[0] = tf32r(pb0.x); b0[1] = tf32r(pb0.y); b0[2] = tf32r(pb0.z); b0[3] = tf32r(pb0.w);
            float* b1 = &Bs[buf][(br + 8) * 132 + bc4];
            b1[0] = tf32r(pb1.x); b1[1] = tf32r(pb1.y); b1[2] = tf32r(pb1.z); b1[3] = tf32r(pb1.w);
        }
    };

    const int aRow = ((lane >> 3) & 1) * 8 + (lane & 7);  // ldmatrix row within m16 tile
    const int aK   = (lane >> 4) * 4;                     // ldmatrix k half

    auto compute = [&](int buf) {
        uint32_t as_u = (uint32_t)__cvta_generic_to_shared(&As[buf][0]);
#pragma unroll
        for (int s = 0; s < 2; s++) {
            uint32_t a[4][4];
#pragma unroll
            for (int i = 0; i < 4; i++) {
                uint32_t ad = as_u + (uint32_t)(((warpM + 16 * i + aRow) * 20 + s * 8 + aK) * 4);
                ldsm4(a[i][0], a[i][1], a[i][2], a[i][3], ad);
            }
            uint32_t b[4][2];
#pragma unroll
            for (int t = 0; t < 4; t++) {
                int n = warpN + 8 * t + (lane >> 2);
                if (BK == 0) {
                    b[t][0] = __float_as_uint(Bs[buf][n * 20 + s * 8 + (lane & 3)]);
                    b[t][1] = __float_as_uint(Bs[buf][n * 20 + s * 8 + 4 + (lane & 3)]);
                } else {
                    b[t][0] = __float_as_uint(Bs[buf][(s * 8 + (lane & 3)) * 132 + n]);
                    b[t][1] = __float_as_uint(Bs[buf][(s * 8 + 4 + (lane & 3)) * 132 + n]);
                }
            }
#pragma unroll
            for (int i = 0; i < 4; i++)
#pragma unroll
                for (int t = 0; t < 4; t++) mma8(acc[i][t], a[i], b[t]);
        }
    };

    const int nc = K >> 4;
    loadAB(0);
    stsAB(0);
    __syncthreads();
    for (int c = 0; c < nc; c++) {
        if (c + 1 < nc) loadAB((c + 1) << 4);
        compute(c & 1);
        if (c + 1 < nc) {
            stsAB((c + 1) & 1);
            __syncthreads();
        }
    }

    // epilogue
#pragma unroll
    for (int i = 0; i < 4; i++) {
        int r = rowBase + warpM + 16 * i + (lane >> 2);
#pragma unroll
        for (int t = 0; t < 4; t++) {
            int cc = colBase + warpN + 8 * t + 2 * (lane & 3);
            float2 v0 = make_float2(acc[i][t][0], acc[i][t][1]);
            float2 v1 = make_float2(acc[i][t][2], acc[i][t][3]);
            if (SCORES) {
                const float* mb = mask + ((size_t)(z & 63) << 16);
                float2 m0 = *(const float2*)&mb[r * 256 + cc];
                float2 m1 = *(const float2*)&mb[(r + 8) * 256 + cc];
                v0.x = fmaf(v0.x, scale, m0.x); v0.y = fmaf(v0.y, scale, m0.y);
                v1.x = fmaf(v1.x, scale, m1.x); v1.y = fmaf(v1.y, scale, m1.y);
            }
            if (GELU) {
                v0.x = gelu1(v0.x); v0.y = gelu1(v0.y);
                v1.x = gelu1(v1.x); v1.y = gelu1(v1.y);
            }
            *(float2*)&C[(size_t)r * N + cc]       = v0;
            *(float2*)&C[(size_t)(r + 8) * N + cc] = v1;
        }
    }
}

// ---------------------------------------------------------------------------
// Weight transpose + tf32 pre-round: dst[n][k] = tf32(src[k][n])
// ---------------------------------------------------------------------------
__global__ void transpose_cvt(const float* __restrict__ src, float* __restrict__ dst,
                              int K, int N)
{
    __shared__ float t[32][33];
    int n0 = blockIdx.x * 32, k0 = blockIdx.y * 32;
    int tx = threadIdx.x, ty = threadIdx.y;
#pragma unroll
    for (int dy = 0; dy < 32; dy += 8)
        t[ty + dy][tx] = src[(size_t)(k0 + ty + dy) * N + n0 + tx];
    __syncthreads();
#pragma unroll
    for (int dy = 0; dy < 32; dy += 8)
        dst[(size_t)(n0 + ty + dy) * K + k0 + tx] = tf32r(t[tx][ty + dy]);
}

// ---------------------------------------------------------------------------
// Roll(-8,-8) + window-partition gather:  [B,H*W,C] -> [512, 256, 256]
// ---------------------------------------------------------------------------
__global__ void permute_fwd(const float4* __restrict__ src, float4* __restrict__ dst)
{
    int e = blockIdx.x * 256 + threadIdx.x;
    int c4 = e & 63;
    int n  = (e >> 6) & 255;
    int w  = e >> 14;
    int b  = w >> 6;
    int widx = w & 63;
    int wy = widx >> 3, wx = widx & 7;
    int i = n >> 4, j = n & 15;
    int h  = (wy * 16 + i + 8) & 127;
    int wc = (wx * 16 + j + 8) & 127;
    size_t sidx = ((size_t)(b * 16384 + h * 128 + wc) << 6) + c4;
    dst[e] = src[sidx];
}

__global__ void permute_bwd(float4* __restrict__ dst, const float4* __restrict__ src)
{
    int e = blockIdx.x * 256 + threadIdx.x;
    int c4 = e & 63;
    int n  = (e >> 6) & 255;
    int w  = e >> 14;
    int b  = w >> 6;
    int widx = w & 63;
    int wy = widx >> 3, wx = widx & 7;
    int i = n >> 4, j = n & 15;
    int h  = (wy * 16 + i + 8) & 127;
    int wc = (wx * 16 + j + 8) & 127;
    size_t didx = ((size_t)(b * 16384 + h * 128 + wc) << 6) + c4;
    dst[didx] = src[e];
}

// ---------------------------------------------------------------------------
// Row softmax over 256 cols. One warp per row.
// ---------------------------------------------------------------------------
__global__ void softmax256(float* __restrict__ S)
{
    int row  = (blockIdx.x << 3) + (threadIdx.x >> 5);
    int lane = threadIdx.x & 31;
    float4* p = (float4*)(S + ((size_t)row << 8)) + lane * 2;
    float4 v0 = p[0], v1 = p[1];

    float mx = fmaxf(fmaxf(fmaxf(v0.x, v0.y), fmaxf(v0.z, v0.w)),
                     fmaxf(fmaxf(v1.x, v1.y), fmaxf(v1.z, v1.w)));
#pragma unroll
    for (int o = 16; o; o >>= 1) mx = fmaxf(mx, __shfl_xor_sync(0xffffffffu, mx, o));

    v0.x = __expf(v0.x - mx); v0.y = __expf(v0.y - mx);
    v0.z = __expf(v0.z - mx); v0.w = __expf(v0.w - mx);
    v1.x = __expf(v1.x - mx); v1.y = __expf(v1.y - mx);
    v1.z = __expf(v1.z - mx); v1.w = __expf(v1.w - mx);

    float s = v0.x + v0.y + v0.z + v0.w + v1.x + v1.y + v1.z + v1.w;
#pragma unroll
    for (int o = 16; o; o >>= 1) s += __shfl_xor_sync(0xffffffffu, s, o);

    float inv = 1.f / s;
    v0.x *= inv; v0.y *= inv; v0.z *= inv; v0.w *= inv;
    v1.x *= inv; v1.y *= inv; v1.z *= inv; v1.w *= inv;
    p[0] = v0; p[1] = v1;
}

// ---------------------------------------------------------------------------
// LayerNorm over 256 cols (eps=1e-5), optional fused residual:
//   Y = (res ? res : 0) + LN(X)*gamma + beta
// One warp per row.
// ---------------------------------------------------------------------------
__global__ void layernorm256(const float* __restrict__ X,
                             const float* __restrict__ gamma,
                             const float* __restrict__ beta,
                             const float* __restrict__ res,
                             float* __restrict__ Y)
{
    int row  = (blockIdx.x << 3) + (threadIdx.x >> 5);
    int lane = threadIdx.x & 31;
    const float4* p = (const float4*)(X + ((size_t)row << 8)) + lane * 2;
    float4 v0 = p[0], v1 = p[1];

    float s  = v0.x + v0.y + v0.z + v0.w + v1.x + v1.y + v1.z + v1.w;
    float sq = v0.x*v0.x + v0.y*v0.y + v0.z*v0.z + v0.w*v0.w
             + v1.x*v1.x + v1.y*v1.y + v1.z*v1.z + v1.w*v1.w;
#pragma unroll
    for (int o = 16; o; o >>= 1) {
        s  += __shfl_xor_sync(0xffffffffu, s,  o);
        sq += __shfl_xor_sync(0xffffffffu, sq, o);
    }
    float mean = s * (1.f / 256.f);
    float var  = sq * (1.f / 256.f) - mean * mean;
    float rstd = rsqrtf(var + 1e-5f);

    const float4* gp = (const float4*)gamma + lane * 2;
    const float4* bp = (const float4*)beta  + lane * 2;
    float4 g0 = gp[0], g1 = gp[1], b0 = bp[0], b1 = bp[1];

    float4 o0, o1;
    o0.x = (v0.x - mean) * rstd * g0.x + b0.x;
    o0.y = (v0.y - mean) * rstd * g0.y + b0.y;
    o0.z = (v0.z - mean) * rstd * g0.z + b0.z;
    o0.w = (v0.w - mean) * rstd * g0.w + b0.w;
    o1.x = (v1.x - mean) * rstd * g1.x + b1.x;
    o1.y = (v1.y - mean) * rstd * g1.y + b1.y;
    o1.z = (v1.z - mean) * rstd * g1.z + b1.z;
    o1.w = (v1.w - mean) * rstd * g1.w + b1.w;

    if (res) {
        const float4* rp = (const float4*)(res + ((size_t)row << 8)) + lane * 2;
        float4 r0 = rp[0], r1 = rp[1];
        o0.x += r0.x; o0.y += r0.y; o0.z += r0.z; o0.w += r0.w;
        o1.x += r1.x; o1.y += r1.y; o1.z += r1.z; o1.w += r1.w;
    }

    float4* q = (float4*)(Y + ((size_t)row << 8)) + lane * 2;
    q[0] = o0; q[1] = o1;
}

__global__ void concat2(const float4* __restrict__ a, const float4* __restrict__ b,
                        float4* __restrict__ o)
{
    size_t e = (size_t)blockIdx.x * 256 + threadIdx.x;
    size_t row = e >> 7;
    int col = (int)(e & 127);
    o[e] = (col < 64) ? a[(row << 6) + col] : b[(row << 6) + col - 64];
}

// ---------------------------------------------------------------------------
// Host orchestration
// ---------------------------------------------------------------------------
static void run_attn_block(const float* xq, const float* xkv, const float* mask,
                           const float* wqT, const float* wkT, const float* wvT,
                           const float* wfcT, const float* gam, const float* bet,
                           const float* res,     // nullptr -> plain LN output
                           float* q, float* k, float* v,
                           float* qw, float* kw, float* vw,
                           float* s, float* ow, float* a, float* t, float* lnOut)
{
    dim3 gm(2, 1024, 1);
    dim3 gw(2, 2, 512);
    gemm_tc<0, false, false><<<gm, 256>>>(xq,  wqT, q, M_TOK, 256, 256, 0, 0, 0, 0.f, nullptr);
    gemm_tc<0, false, false><<<gm, 256>>>(xkv, wkT, k, M_TOK, 256, 256, 0, 0, 0, 0.f, nullptr);
    gemm_tc<0, false, false><<<gm, 256>>>(xkv, wvT, v, M_TOK, 256, 256, 0, 0, 0, 0.f, nullptr);
    permute_fwd<<<32768, 256>>>((const float4*)q, (float4*)qw);
    permute_fwd<<<32768, 256>>>((const float4*)k, (float4*)kw);
    permute_fwd<<<32768, 256>>>((const float4*)v, (float4*)vw);
    // scores = Qw @ Kw^T / 16 + mask[w%64]   (Kw is N-major: [n][k=c])
    gemm_tc<0, true, false><<<gw, 256>>>(qw, kw, s, 256, 256, 256,
                                         65536, 65536, 65536, 1.f / 16.f, mask);
    softmax256<<<16384, 256>>>(s);
    // Ow = P @ Vw   (Vw is K-major: [k=m][n=c])
    gemm_tc<1, false, false><<<gw, 256>>>(s, vw, ow, 256, 256, 256,
                                          65536, 65536, 65536, 0.f, nullptr);
    permute_bwd<<<32768, 256>>>((float4*)a, (const float4*)ow);
    gemm_tc<0, false, false><<<gm, 256>>>(a, wfcT, t, M_TOK, 256, 256, 0, 0, 0, 0.f, nullptr);
    layernorm256<<<16384, 256>>>(t, gam, bet, res, lnOut);
}

extern "C" void kernel_launch(void* const* d_in, const int* in_sizes, int n_in,
                              void* d_out, int out_size)
{
    const float* feat0 = (const float*)d_in[0];
    const float* feat1 = (const float*)d_in[1];
    const float* mask  = (const float*)d_in[2];
    const float* iwq  = (const float*)d_in[6];
    const float* iwk  = (const float*)d_in[7];
    const float* iwv  = (const float*)d_in[8];
    const float* iwfc = (const float*)d_in[9];
    const float* ig   = (const float*)d_in[10];
    const float* ib   = (const float*)d_in[11];
    const float* ewq  = (const float*)d_in[12];
    const float* ewk  = (const float*)d_in[13];
    const float* ewv  = (const float*)d_in[14];
    const float* ewfc = (const float*)d_in[15];
    const float* eg   = (const float*)d_in[16];
    const float* eb   = (const float*)d_in[17];
    const float* w1   = (const float*)d_in[18];
    const float* w2   = (const float*)d_in[19];
    const float* fg   = (const float*)d_in[20];
    const float* fb   = (const float*)d_in[21];
    float* out = (float*)d_out;

    float *q, *k, *v, *qw, *kw, *vw, *s, *ow, *a, *t, *ln, *f0, *cat, *h, *wT;
    cudaGetSymbolAddress((void**)&q,  g_q);
    cudaGetSymbolAddress((void**)&k,  g_k);
    cudaGetSymbolAddress((void**)&v,  g_v);
    cudaGetSymbolAddress((void**)&qw, g_qw);
    cudaGetSymbolAddress((void**)&kw, g_kw);
    cudaGetSymbolAddress((void**)&vw, g_vw);
    cudaGetSymbolAddress((void**)&s,  g_s);
    cudaGetSymbolAddress((void**)&ow, g_ow);
    cudaGetSymbolAddress((void**)&a,  g_a);
    cudaGetSymbolAddress((void**)&t,  g_t);
    cudaGetSymbolAddress((void**)&ln, g_ln);
    cudaGetSymbolAddress((void**)&f0, g_f0);
    cudaGetSymbolAddress((void**)&cat, g_cat);
    cudaGetSymbolAddress((void**)&h,  g_h);
    cudaGetSymbolAddress((void**)&wT, g_wT);

    // Pre-transpose (+tf32 round) all weights: dst[n][k] = tf32(src[k][n])
    float* iwqT  = wT;            // 256x256 each
    float* iwkT  = wT + 65536;
    float* iwvT  = wT + 131072;
    float* iwfcT = wT + 196608;
    float* ewqT  = wT + 262144;
    float* ewkT  = wT + 327680;
    float* ewvT  = wT + 393216;
    float* ewfcT = wT + 458752;
    float* w1T   = wT + 524288;   // [2048,512]
    float* w2T   = wT + 1572864;  // [256,2048]
    dim3 tb(32, 8);
    transpose_cvt<<<dim3(8, 8),  tb>>>(iwq,  iwqT,  256, 256);
    transpose_cvt<<<dim3(8, 8),  tb>>>(iwk,  iwkT,  256, 256);
    transpose_cvt<<<dim3(8, 8),  tb>>>(iwv,  iwvT,  256, 256);
    transpose_cvt<<<dim3(8, 8),  tb>>>(iwfc, iwfcT, 256, 256);
    transpose_cvt<<<dim3(8, 8),  tb>>>(ewq,  ewqT,  256, 256);
    transpose_cvt<<<dim3(8, 8),  tb>>>(ewk,  ewkT,  256, 256);
    transpose_cvt<<<dim3(8, 8),  tb>>>(ewv,  ewvT,  256, 256);
    transpose_cvt<<<dim3(8, 8),  tb>>>(ewfc, ewfcT, 256, 256);
    transpose_cvt<<<dim3(64, 16), tb>>>(w1, w1T, 512, 2048);
    transpose_cvt<<<dim3(8, 64),  tb>>>(w2, w2T, 2048, 256);

    // ---- Block 1 (intra): f0 = feat0 + LN(attn(feat0)) ----
    run_attn_block(feat0, feat0, mask, iwqT, iwkT, iwvT, iwfcT, ig, ib,
                   /*res=*/feat0,
                   q, k, v, qw, kw, vw, s, ow, a, t, f0);

    // ---- Block 2 (inter): ln = LN(attn(f0, feat1))  (no residual; feeds concat) ----
    run_attn_block(f0, feat1, mask, ewqT, ewkT, ewvT, ewfcT, eg, eb,
                   /*res=*/nullptr,
                   q, k, v, qw, kw, vw, s, ow, a, t, ln);

    // FFN: cat=[f0, ln] @ w1 -> gelu (fused) -> @ w2 -> LN + residual(f0)
    concat2<<<65536, 256>>>((const float4*)f0, (const float4*)ln, (float4*)cat);
    gemm_tc<0, false, true><<<dim3(16, 1024, 1), 256>>>(cat, w1T, h,
                                                        M_TOK, 2048, 512, 0, 0, 0, 0.f, nullptr);
    gemm_tc<0, false, false><<<dim3(2, 1024, 1), 256>>>(h, w2T, t,
                                                        M_TOK, 256, 2048, 0, 0, 0, 0.f, nullptr);
    layernorm256<<<16384, 256>>>(t, fg, fb, f0, out);
}

// round 12
// speedup vs baseline: 2.7331x; 1.0216x over previous
#include <cuda_runtime.h>
#include <math.h>
#include <stdint.h>

// ---------------------------------------------------------------------------
// Problem constants: B=8, H=W=128, NW=8, D=256
//   tokens M = 8*128*128 = 131072; windows = 512, window tokens N = 256
// ---------------------------------------------------------------------------
#define M_TOK 131072
#define WBUF  33554432          // elements per window-space buffer [512*256,256]

// Scratch (device globals: allocation-free kernel_launch)
__device__ float g_qkvw[100663296]; // qw | kw | vw, each WBUF, contiguous
__device__ float g_s [33554432];    // scores
__device__ float g_a [33554432];    // attn out, token-space
__device__ float g_t [33554432];
__device__ float g_ln[33554432];
__device__ float g_f0[33554432];
__device__ float g_h [268435456];   // [131072, 2048]
__device__ float g_wT[2097152];     // transposed+tf32 weights

// ---------------------------------------------------------------------------
// helpers
// ---------------------------------------------------------------------------
__device__ __forceinline__ float tf32r(float x) {
    float r;
    asm("cvt.rna.tf32.f32 %0, %1;" : "=f"(r) : "f"(x));
    return r;
}
__device__ __forceinline__ void ldsm4(uint32_t& r0, uint32_t& r1, uint32_t& r2,
                                      uint32_t& r3, uint32_t a) {
    asm volatile("ldmatrix.sync.aligned.m8n8.x4.shared.b16 {%0,%1,%2,%3}, [%4];"
                 : "=r"(r0), "=r"(r1), "=r"(r2), "=r"(r3) : "r"(a));
}
__device__ __forceinline__ void mma8(float* c, const uint32_t* a, const uint32_t* b) {
    asm volatile(
        "mma.sync.aligned.m16n8k8.row.col.f32.tf32.tf32.f32 "
        "{%0,%1,%2,%3},{%4,%5,%6,%7},{%8,%9},{%0,%1,%2,%3};"
        : "+f"(c[0]), "+f"(c[1]), "+f"(c[2]), "+f"(c[3])
        : "r"(a[0]), "r"(a[1]), "r"(a[2]), "r"(a[3]), "r"(b[0]), "r"(b[1]));
}
__device__ __forceinline__ float gelu1(float x) {
    return 0.5f * x * (1.f + erff(x * 0.70710678118654752f));
}

// token index -> flattened window row index (w*256+n); roll(-8,-8)+partition
__device__ __forceinline__ int win_from_tok(int t) {
    int b = t >> 14, h = (t >> 7) & 127, c = t & 127;
    int h2 = (h + 120) & 127, c2 = (c + 120) & 127;
    int w = (b << 6) + ((h2 >> 4) << 3) + (c2 >> 4);
    int n = ((h2 & 15) << 4) + (c2 & 15);
    return (w << 8) + n;
}
// (window z, row n) -> token index; inverse map
__device__ __forceinline__ int tok_from_win(int z, int n) {
    int b = z >> 6, wy = (z >> 3) & 7, wx = z & 7;
    int h = ((wy << 4) + (n >> 4) + 8) & 127;
    int c = ((wx << 4) + (n & 15) + 8) & 127;
    return (b << 14) + (h << 7) + c;
}

// ---------------------------------------------------------------------------
// Tensor-core tf32 GEMM. CTA tile 128x128, 8 warps of 64x32, K-chunk 16,
// double-buffered smem + register prefetch.
//   BK=0 : B is N-major [N,K]  -> C = A @ B^T
//   BK=1 : B is K-major [K,N]  -> C = A @ B
//   CMAP=0: linear C
//   CMAP=1: row r -> win_from_tok(r), C one window buffer [512*256,256]
//   CMAP=2: row n -> tok_from_win(z,n), C is [131072,256]; pass sC=0
//   CMAP=3: row r -> win_from_tok(r), col cc -> buffer (cc>>8)*WBUF + (cc&255)
//           (fused multi-output projection; buffers contiguous from C)
//   SCORES: C = C*scale + mask[z&63]     (CMAP must be 0)
//   GELU: exact gelu on accumulator before store
//   ACAT: logical A = concat(A, A2) along K; both [M,256], K must be 512
// ---------------------------------------------------------------------------
template<int BK, int CMAP, bool SCORES, bool GELU, bool ACAT>
__global__ __launch_bounds__(256)
void gemm_tc(const float* __restrict__ A, const float* __restrict__ A2,
             const float* __restrict__ B,
             float* __restrict__ C, int M, int N, int K,
             size_t sA, size_t sB, size_t sC,
             float scale, const float* __restrict__ mask)
{
    __shared__ float As[2][2560];   // 128 rows x (16+4) pad
    __shared__ float Bs[2][2560];   // NMAJ: 128x20 ; KMAJ: 16x132

    const int tid  = threadIdx.x;
    const int lane = tid & 31;
    const int warp = tid >> 5;
    const int warpM = (warp & 1) * 64;
    const int warpN = (warp >> 1) * 32;
    const int rowBase = blockIdx.y * 128;
    const int colBase = blockIdx.x * 128;
    const int z = blockIdx.z;
    A += (size_t)z * sA;
    B += (size_t)z * sB;
    C += (size_t)z * sC;

    float acc[4][4][4];
#pragma unroll
    for (int i = 0; i < 4; i++)
#pragma unroll
        for (int t = 0; t < 4; t++)
#pragma unroll
            for (int r = 0; r < 4; r++) acc[i][t][r] = 0.f;

    // global-load coordinates
    const int ar  = tid >> 2;          // 0..63 (rows ar, ar+64)
    const int ac4 = (tid & 3) << 2;    // k offset within 16-chunk
    const int br  = tid >> 5;          // 0..7  (KMAJ rows br, br+8)
    const int bc4 = (tid & 31) << 2;   // n offset 0..124

    float4 pa0, pa1, pb0, pb1;

    auto loadAB = [&](int k0) {
        if (ACAT) {
            int kk = k0 + ac4;
            const float* base = (kk < 256) ? A : A2;
            int ko = kk & 255;
            pa0 = *(const float4*)&base[((size_t)(rowBase + ar)      << 8) + ko];
            pa1 = *(const float4*)&base[((size_t)(rowBase + ar + 64) << 8) + ko];
        } else {
            pa0 = *(const float4*)&A[(size_t)(rowBase + ar)      * K + k0 + ac4];
            pa1 = *(const float4*)&A[(size_t)(rowBase + ar + 64) * K + k0 + ac4];
        }
        if (BK == 0) {
            pb0 = *(const float4*)&B[(size_t)(colBase + ar)      * K + k0 + ac4];
            pb1 = *(const float4*)&B[(size_t)(colBase + ar + 64) * K + k0 + ac4];
        } else {
            pb0 = *(const float4*)&B[(size_t)(k0 + br)     * N + colBase + bc4];
            pb1 = *(const float4*)&B[(size_t)(k0 + br + 8) * N + colBase + bc4];
        }
    };
    auto stsAB = [&](int buf) {
        float* a0 = &As[buf][ar * 20 + ac4];
        a0[0] = tf32r(pa0.x); a0[1] = tf32r(pa0.y); a0[2] = tf32r(pa0.z); a0[3] = tf32r(pa0.w);
        float* a1 = &As[buf][(ar + 64) * 20 + ac4];
        a1[0] = tf32r(pa1.x); a1[1] = tf32r(pa1.y); a1[2] = tf32r(pa1.z); a1[3] = tf32r(pa1.w);
        if (BK == 0) {
            float* b0 = &Bs[buf][ar * 20 + ac4];
            b0[0] = tf32r(pb0.x); b0[1] = tf32r(pb0.y); b0[2] = tf32r(pb0.z); b0[3] = tf32r(pb0.w);
            float* b1 = &Bs[buf][(ar + 64) * 20 + ac4];
            b1[0] = tf32r(pb1.x); b1[1] = tf32r(pb1.y); b1[2] = tf32r(pb1.z); b1[3] = tf32r(pb1.w);
        } else {
            float* b0 = &Bs[buf][br * 132 + bc4];
            b0[0] = tf32r(pb0.x); b0[1] = tf32r(pb0.y); b0[2] = tf32r(pb0.z); b0[3] = tf32r(pb0.w);
            float* b1 = &Bs[buf][(br + 8) * 132 + bc4];
            b1[0] = tf32r(pb1.x); b1[1] = tf32r(pb1.y); b1[2] = tf32r(pb1.z); b1[3] = tf32r(pb1.w);
        }
    };

    const int aRow = ((lane >> 3) & 1) * 8 + (lane & 7);  // ldmatrix row within m16 tile
    const int aK   = (lane >> 4) * 4;                     // ldmatrix k half

    auto compute = [&](int buf) {
        uint32_t as_u = (uint32_t)__cvta_generic_to_shared(&As[buf][0]);
#pragma unroll
        for (int s = 0; s < 2; s++) {
            uint32_t a[4][4];
#pragma unroll
            for (int i = 0; i < 4; i++) {
                uint32_t ad = as_u + (uint32_t)(((warpM + 16 * i + aRow) * 20 + s * 8 + aK) * 4);
                ldsm4(a[i][0], a[i][1], a[i][2], a[i][3], ad);
            }
            uint32_t b[4][2];
#pragma unroll
            for (int t = 0; t < 4; t++) {
                int n = warpN + 8 * t + (lane >> 2);
                if (BK == 0) {
                    b[t][0] = __float_as_uint(Bs[buf][n * 20 + s * 8 + (lane & 3)]);
                    b[t][1] = __float_as_uint(Bs[buf][n * 20 + s * 8 + 4 + (lane & 3)]);
                } else {
                    b[t][0] = __float_as_uint(Bs[buf][(s * 8 + (lane & 3)) * 132 + n]);
                    b[t][1] = __float_as_uint(Bs[buf][(s * 8 + 4 + (lane & 3)) * 132 + n]);
                }
            }
#pragma unroll
            for (int i = 0; i < 4; i++)
#pragma unroll
                for (int t = 0; t < 4; t++) mma8(acc[i][t], a[i], b[t]);
        }
    };

    const int nc = K >> 4;
    loadAB(0);
    stsAB(0);
    __syncthreads();
    for (int c = 0; c < nc; c++) {
        if (c + 1 < nc) loadAB((c + 1) << 4);
        compute(c & 1);
        if (c + 1 < nc) {
            stsAB((c + 1) & 1);
            __syncthreads();
        }
    }

    // epilogue
#pragma unroll
    for (int i = 0; i < 4; i++) {
        int r = rowBase + warpM + 16 * i + (lane >> 2);
#pragma unroll
        for (int t = 0; t < 4; t++) {
            int cc = colBase + warpN + 8 * t + 2 * (lane & 3);
            float2 v0 = make_float2(acc[i][t][0], acc[i][t][1]);
            float2 v1 = make_float2(acc[i][t][2], acc[i][t][3]);
            if (SCORES) {
                const float* mb = mask + ((size_t)(z & 63) << 16);
                float2 m0 = *(const float2*)&mb[r * 256 + cc];
                float2 m1 = *(const float2*)&mb[(r + 8) * 256 + cc];
                v0.x = fmaf(v0.x, scale, m0.x); v0.y = fmaf(v0.y, scale, m0.y);
                v1.x = fmaf(v1.x, scale, m1.x); v1.y = fmaf(v1.y, scale, m1.y);
            }
            if (GELU) {
                v0.x = gelu1(v0.x); v0.y = gelu1(v0.y);
                v1.x = gelu1(v1.x); v1.y = gelu1(v1.y);
            }
            size_t o0, o1;
            if (CMAP == 1) {        // token row -> window-space row
                o0 = ((size_t)win_from_tok(r)     << 8) + cc;
                o1 = ((size_t)win_from_tok(r + 8) << 8) + cc;
            } else if (CMAP == 2) { // window row (z, r) -> token row
                o0 = ((size_t)tok_from_win(z, r)     << 8) + cc;
                o1 = ((size_t)tok_from_win(z, r + 8) << 8) + cc;
            } else if (CMAP == 3) { // multi-output window scatter
                size_t bufo = (size_t)(cc >> 8) * WBUF;
                int c2 = cc & 255;
                o0 = bufo + ((size_t)win_from_tok(r)     << 8) + c2;
                o1 = bufo + ((size_t)win_from_tok(r + 8) << 8) + c2;
            } else {
                o0 = (size_t)r * N + cc;
                o1 = (size_t)(r + 8) * N + cc;
            }
            *(float2*)&C[o0] = v0;
            *(float2*)&C[o1] = v1;
        }
    }
}

// ---------------------------------------------------------------------------
// Weight transpose + tf32 pre-round: dst[n][k] = tf32(src[k][n])
// ---------------------------------------------------------------------------
__global__ void transpose_cvt(const float* __restrict__ src, float* __restrict__ dst,
                              int K, int N)
{
    __shared__ float t[32][33];
    int n0 = blockIdx.x * 32, k0 = blockIdx.y * 32;
    int tx = threadIdx.x, ty = threadIdx.y;
#pragma unroll
    for (int dy = 0; dy < 32; dy += 8)
        t[ty + dy][tx] = src[(size_t)(k0 + ty + dy) * N + n0 + tx];
    __syncthreads();
#pragma unroll
    for (int dy = 0; dy < 32; dy += 8)
        dst[(size_t)(n0 + ty + dy) * K + k0 + tx] = tf32r(t[tx][ty + dy]);
}

// ---------------------------------------------------------------------------
// Row softmax over 256 cols. One warp per row.
// ---------------------------------------------------------------------------
__global__ void softmax256(float* __restrict__ S)
{
    int row  = (blockIdx.x << 3) + (threadIdx.x >> 5);
    int lane = threadIdx.x & 31;
    float4* p = (float4*)(S + ((size_t)row << 8)) + lane * 2;
    float4 v0 = p[0], v1 = p[1];

    float mx = fmaxf(fmaxf(fmaxf(v0.x, v0.y), fmaxf(v0.z, v0.w)),
                     fmaxf(fmaxf(v1.x, v1.y), fmaxf(v1.z, v1.w)));
#pragma unroll
    for (int o = 16; o; o >>= 1) mx = fmaxf(mx, __shfl_xor_sync(0xffffffffu, mx, o));

    v0.x = __expf(v0.x - mx); v0.y = __expf(v0.y - mx);
    v0.z = __expf(v0.z - mx); v0.w = __expf(v0.w - mx);
    v1.x = __expf(v1.x - mx); v1.y = __expf(v1.y - mx);
    v1.z = __expf(v1.z - mx); v1.w = __expf(v1.w - mx);

    float s = v0.x + v0.y + v0.z + v0.w + v1.x + v1.y + v1.z + v1.w;
#pragma unroll
    for (int o = 16; o; o >>= 1) s += __shfl_xor_sync(0xffffffffu, s, o);

    float inv = 1.f / s;
    v0.x *= inv; v0.y *= inv; v0.z *= inv; v0.w *= inv;
    v1.x *= inv; v1.y *= inv; v1.z *= inv; v1.w *= inv;
    p[0] = v0; p[1] = v1;
}

// ---------------------------------------------------------------------------
// LayerNorm over 256 cols (eps=1e-5), optional fused residual:
//   Y = (res ? res : 0) + LN(X)*gamma + beta
// ---------------------------------------------------------------------------
__global__ void layernorm256(const float* __restrict__ X,
                             const float* __restrict__ gamma,
                             const float* __restrict__ beta,
                             const float* __restrict__ res,
                             float* __restrict__ Y)
{
    int row  = (blockIdx.x << 3) + (threadIdx.x >> 5);
    int lane = threadIdx.x & 31;
    const float4* p = (const float4*)(X + ((size_t)row << 8)) + lane * 2;
    float4 v0 = p[0], v1 = p[1];

    float s  = v0.x + v0.y + v0.z + v0.w + v1.x + v1.y + v1.z + v1.w;
    float sq = v0.x*v0.x + v0.y*v0.y + v0.z*v0.z + v0.w*v0.w
             + v1.x*v1.x + v1.y*v1.y + v1.z*v1.z + v1.w*v1.w;
#pragma unroll
    for (int o = 16; o; o >>= 1) {
        s  += __shfl_xor_sync(0xffffffffu, s,  o);
        sq += __shfl_xor_sync(0xffffffffu, sq, o);
    }
    float mean = s * (1.f / 256.f);
    float var  = sq * (1.f / 256.f) - mean * mean;
    float rstd = rsqrtf(var + 1e-5f);

    const float4* gp = (const float4*)gamma + lane * 2;
    const float4* bp = (const float4*)beta  + lane * 2;
    float4 g0 = gp[0], g1 = gp[1], b0 = bp[0], b1 = bp[1];

    float4 o0, o1;
    o0.x = (v0.x - mean) * rstd * g0.x + b0.x;
    o0.y = (v0.y - mean) * rstd * g0.y + b0.y;
    o0.z = (v0.z - mean) * rstd * g0.z + b0.z;
    o0.w = (v0.w - mean) * rstd * g0.w + b0.w;
    o1.x = (v1.x - mean) * rstd * g1.x + b1.x;
    o1.y = (v1.y - mean) * rstd * g1.y + b1.y;
    o1.z = (v1.z - mean) * rstd * g1.z + b1.z;
    o1.w = (v1.w - mean) * rstd * g1.w + b1.w;

    if (res) {
        const float4* rp = (const float4*)(res + ((size_t)row << 8)) + lane * 2;
        float4 r0 = rp[0], r1 = rp[1];
        o0.x += r0.x; o0.y += r0.y; o0.z += r0.z; o0.w += r0.w;
        o1.x += r1.x; o1.y += r1.y; o1.z += r1.z; o1.w += r1.w;
    }

    float4* q = (float4*)(Y + ((size_t)row << 8)) + lane * 2;
    q[0] = o0; q[1] = o1;
}

// ---------------------------------------------------------------------------
// Host orchestration: attention tail (scores..LN) shared by both blocks
// ---------------------------------------------------------------------------
static void attn_tail(const float* mask, const float* wfcT,
                      const float* gam, const float* bet, const float* res,
                      float* qw, float* kw, float* vw,
                      float* s, float* a, float* t, float* lnOut)
{
    dim3 gm(2, 1024, 1);
    dim3 gw(2, 2, 512);
    // scores = Qw @ Kw^T / 16 + mask[w%64]
    gemm_tc<0, 0, true, false, false><<<gw, 256>>>(qw, nullptr, kw, s, 256, 256, 256,
                                                   65536, 65536, 65536, 1.f / 16.f, mask);
    softmax256<<<16384, 256>>>(s);
    // attn_out = P @ Vw, scattered back to token order
    gemm_tc<1, 2, false, false, false><<<gw, 256>>>(s, nullptr, vw, a, 256, 256, 256,
                                                    65536, 65536, 0, 0.f, nullptr);
    // FC + LN(+res)
    gemm_tc<0, 0, false, false, false><<<gm, 256>>>(a, nullptr, wfcT, t,
                                                    M_TOK, 256, 256, 0, 0, 0, 0.f, nullptr);
    layernorm256<<<16384, 256>>>(t, gam, bet, res, lnOut);
}

extern "C" void kernel_launch(void* const* d_in, const int* in_sizes, int n_in,
                              void* d_out, int out_size)
{
    const float* feat0 = (const float*)d_in[0];
    const float* feat1 = (const float*)d_in[1];
    const float* mask  = (const float*)d_in[2];
    const float* iwq  = (const float*)d_in[6];
    const float* iwk  = (const float*)d_in[7];
    const float* iwv  = (const float*)d_in[8];
    const float* iwfc = (const float*)d_in[9];
    const float* ig   = (const float*)d_in[10];
    const float* ib   = (const float*)d_in[11];
    const float* ewq  = (const float*)d_in[12];
    const float* ewk  = (const float*)d_in[13];
    const float* ewv  = (const float*)d_in[14];
    const float* ewfc = (const float*)d_in[15];
    const float* eg   = (const float*)d_in[16];
    const float* eb   = (const float*)d_in[17];
    const float* w1   = (const float*)d_in[18];
    const float* w2   = (const float*)d_in[19];
    const float* fg   = (const float*)d_in[20];
    const float* fb   = (const float*)d_in[21];
    float* out = (float*)d_out;

    float *qkvw, *s, *a, *t, *ln, *f0, *h, *wT;
    cudaGetSymbolAddress((void**)&qkvw, g_qkvw);
    cudaGetSymbolAddress((void**)&s,  g_s);
    cudaGetSymbolAddress((void**)&a,  g_a);
    cudaGetSymbolAddress((void**)&t,  g_t);
    cudaGetSymbolAddress((void**)&ln, g_ln);
    cudaGetSymbolAddress((void**)&f0, g_f0);
    cudaGetSymbolAddress((void**)&h,  g_h);
    cudaGetSymbolAddress((void**)&wT, g_wT);

    float* qw = qkvw;
    float* kw = qkvw + WBUF;
    float* vw = qkvw + 2 * (size_t)WBUF;

    // Pre-transpose (+tf32 round) all weights: dst[n][k] = tf32(src[k][n])
    // i{q,k,v} contiguous -> one [768,256] block; e{k,v} contiguous -> [512,256]
    float* iwqT  = wT;            // 256x256 each
    float* iwkT  = wT + 65536;
    float* iwvT  = wT + 131072;
    float* iwfcT = wT + 196608;
    float* ewqT  = wT + 262144;
    float* ewkT  = wT + 327680;
    float* ewvT  = wT + 393216;
    float* ewfcT = wT + 458752;
    float* w1T   = wT + 524288;   // [2048,512]
    float* w2T   = wT + 1572864;  // [256,2048]
    dim3 tb(32, 8);
    transpose_cvt<<<dim3(8, 8),  tb>>>(iwq,  iwqT,  256, 256);
    transpose_cvt<<<dim3(8, 8),  tb>>>(iwk,  iwkT,  256, 256);
    transpose_cvt<<<dim3(8, 8),  tb>>>(iwv,  iwvT,  256, 256);
    transpose_cvt<<<dim3(8, 8),  tb>>>(iwfc, iwfcT, 256, 256);
    transpose_cvt<<<dim3(8, 8),  tb>>>(ewq,  ewqT,  256, 256);
    transpose_cvt<<<dim3(8, 8),  tb>>>(ewk,  ewkT,  256, 256);
    transpose_cvt<<<dim3(8, 8),  tb>>>(ewv,  ewvT,  256, 256);
    transpose_cvt<<<dim3(8, 8),  tb>>>(ewfc, ewfcT, 256, 256);
    transpose_cvt<<<dim3(64, 16), tb>>>(w1, w1T, 512, 2048);
    transpose_cvt<<<dim3(8, 64),  tb>>>(w2, w2T, 2048, 256);

    // ---- Block 1 (intra): q,k,v all from feat0 -> one merged N=768 GEMM ----
    gemm_tc<0, 3, false, false, false><<<dim3(6, 1024, 1), 256>>>(
        feat0, nullptr, iwqT, qkvw, M_TOK, 768, 256, 0, 0, 0, 0.f, nullptr);
    attn_tail(mask, iwfcT, ig, ib, /*res=*/feat0, qw, kw, vw, s, a, t, f0);

    // ---- Block 2 (inter): q from f0; k,v merged from feat1 ----
    gemm_tc<0, 1, false, false, false><<<dim3(2, 1024, 1), 256>>>(
        f0, nullptr, ewqT, qw, M_TOK, 256, 256, 0, 0, 0, 0.f, nullptr);
    gemm_tc<0, 3, false, false, false><<<dim3(4, 1024, 1), 256>>>(
        feat1, nullptr, ewkT, kw, M_TOK, 512, 256, 0, 0, 0, 0.f, nullptr);
    attn_tail(mask, ewfcT, eg, eb, /*res=*/nullptr, qw, kw, vw, s, a, t, ln);

    // FFN: [f0|ln] @ w1 -> gelu (fused) -> @ w2 -> LN + residual(f0)
    gemm_tc<0, 0, false, true, true><<<dim3(16, 1024, 1), 256>>>(f0, ln, w1T, h,
                                                                 M_TOK, 2048, 512,
                                                                 0, 0, 0, 0.f, nullptr);
    gemm_tc<0, 0, false, false, false><<<dim3(2, 1024, 1), 256>>>(h, nullptr, w2T, t,
                                                                  M_TOK, 256, 2048,
                                                                  0, 0, 0, 0.f, nullptr);
    layernorm256<<<16384, 256>>>(t, fg, fb, f0, out);
}